// round 1
// baseline (speedup 1.0000x reference)
#include <cuda_runtime.h>
#include <math.h>

// ---------------- problem constants ----------------
#define LNUM 4
#define BB   4
#define TT   2048
#define DD   1024
#define HH   1024
#define FF   256
#define MTOT (BB*TT)          // 8192
#define NCHUNK 16
#define CL   (TT/NCHUNK)      // 128

// ---------------- GEMM tile config ----------------
#define BM 128
#define BN 128
#define BK 16

// ---------------- scratch (device globals; no allocs allowed) ----------------
__device__ float g_xn[MTOT*DD];          // 32 MB
__device__ float g_bu[MTOT*2*HH];        // 64 MB
__device__ float g_hs[MTOT*2*HH];        // 64 MB
__device__ float g_y [MTOT*DD];          // 32 MB
__device__ float g_g [MTOT*2*DD];        // 64 MB
__device__ float g_lam_re[LNUM*HH];
__device__ float g_lam_im[LNUM*HH];
__device__ float g_gam  [LNUM*HH];
__device__ float g_sum_re[BB*NCHUNK*HH];
__device__ float g_sum_im[BB*NCHUNK*HH];
__device__ float g_car_re[BB*NCHUNK*HH];
__device__ float g_car_im[BB*NCHUNK*HH];

// ---------------- f32x2 helpers ----------------
__device__ __forceinline__ unsigned long long pk2(float x, float y) {
    unsigned long long r;
    asm("mov.b64 %0, {%1, %2};" : "=l"(r) : "f"(x), "f"(y));
    return r;
}
__device__ __forceinline__ unsigned long long fma2(unsigned long long a,
                                                   unsigned long long b,
                                                   unsigned long long c) {
    unsigned long long d;
    asm("fma.rn.f32x2 %0, %1, %2, %3;" : "=l"(d) : "l"(a), "l"(b), "l"(c));
    return d;
}

__device__ __forceinline__ float gelu_exact(float v) {
    return 0.5f * v * (1.0f + erff(v * 0.70710678118654752f));
}

// ---------------- parameter prep ----------------
__global__ void prep_kernel(const float* __restrict__ nu_log,
                            const float* __restrict__ theta_log) {
    int i = blockIdx.x * blockDim.x + threadIdx.x;   // L*H
    float nu = expf(nu_log[i]);
    float th = expf(theta_log[i]);
    float r  = expf(-nu);
    g_lam_re[i] = r * cosf(th);
    g_lam_im[i] = r * sinf(th);
    g_gam[i]    = sqrtf(1.0f - expf(-2.0f * nu) + 1e-5f);
}

// ---------------- layernorm ----------------
__global__ void ln_kernel(const float* __restrict__ x,
                          const float* __restrict__ sc,
                          const float* __restrict__ bi,
                          float* __restrict__ o) {
    __shared__ float red[16];
    int row = blockIdx.x;
    int tid = threadIdx.x;
    const float* xr = x + (size_t)row * DD;
    float4 v = *(const float4*)(xr + tid * 4);
    float s  = v.x + v.y + v.z + v.w;
    float ss = v.x*v.x + v.y*v.y + v.z*v.z + v.w*v.w;
    #pragma unroll
    for (int off = 16; off; off >>= 1) {
        s  += __shfl_xor_sync(0xffffffffu, s,  off);
        ss += __shfl_xor_sync(0xffffffffu, ss, off);
    }
    int wid = tid >> 5;
    if ((tid & 31) == 0) { red[wid] = s; red[8 + wid] = ss; }
    __syncthreads();
    float S = 0.f, SS = 0.f;
    #pragma unroll
    for (int w = 0; w < 8; w++) { S += red[w]; SS += red[8 + w]; }
    float mu  = S * (1.0f / DD);
    float var = SS * (1.0f / DD) - mu * mu;
    float rstd = rsqrtf(var + 1e-5f);
    float4 s4 = *(const float4*)(sc + tid * 4);
    float4 b4 = *(const float4*)(bi + tid * 4);
    float4 ov;
    ov.x = (v.x - mu) * rstd * s4.x + b4.x;
    ov.y = (v.y - mu) * rstd * s4.y + b4.y;
    ov.z = (v.z - mu) * rstd * s4.z + b4.z;
    ov.w = (v.w - mu) * rstd * s4.w + b4.w;
    *(float4*)(o + (size_t)row * DD + tid * 4) = ov;
}

// ---------------- generic fp32 GEMM:  C[m,n] = sum_k A[m,k] * W(n,k)  ----------------
// W(n,k) resolved via optional N-split (two weight matrices stacked over n) or
// K-split (two weight matrices concatenated over k, second multiplied by w1sign).
// epi: 0 = +bias (per-n, split like W)   1 = *epi_n[n & (HH-1)]   2 = gelu(acc + epi_m[m,n]*epi_n[n])
__global__ __launch_bounds__(256, 2)
void gemm_f32(const float* __restrict__ A, int lda,
              const float* __restrict__ W0, const float* __restrict__ W1,
              int ldw, int nsplit, int ksplit, float w1sign,
              const float* __restrict__ bias0, const float* __restrict__ bias1,
              float* __restrict__ C, int ldc,
              int K,
              int epi, const float* __restrict__ epi_m, const float* __restrict__ epi_n) {
    __shared__ float As[2][BK][BM + 4];
    __shared__ float Ws[2][BK][BN + 4];

    const int tid  = threadIdx.x;
    const int m0   = blockIdx.y * BM;
    const int n0   = blockIdx.x * BN;
    const int rowL = tid >> 2;          // 0..63
    const int col4 = (tid & 3) * 4;     // 0,4,8,12

    const float* biasb = nullptr;
    if (bias0)
        biasb = (nsplit && n0 >= nsplit) ? (bias1 + (n0 - nsplit)) : (bias0 + n0);

    const float* WbaseN = (nsplit && n0 >= nsplit)
                        ? (W1 + (size_t)(n0 - nsplit) * ldw)
                        : (W0 + (size_t)n0 * ldw);
    const float* Aptr = A + (size_t)m0 * lda;

    const int ntiles = K / BK;

    float4 ra[2], rw[2];
    float sgnS;
    {   // prefetch tile 0
        const float* wb; int keff;
        if (ksplit) {
            wb = W0 + (size_t)n0 * ldw; keff = 0; sgnS = 1.f;
        } else { wb = WbaseN; keff = 0; sgnS = 1.f; }
        #pragma unroll
        for (int p = 0; p < 2; p++) {
            ra[p] = *(const float4*)(Aptr + (size_t)(rowL + 64*p) * lda + col4);
            rw[p] = *(const float4*)(wb   + (size_t)(rowL + 64*p) * ldw + keff + col4);
        }
    }
    int buf = 0;
    #pragma unroll
    for (int p = 0; p < 2; p++) {
        int r = rowL + 64*p;
        As[0][col4+0][r] = ra[p].x;  As[0][col4+1][r] = ra[p].y;
        As[0][col4+2][r] = ra[p].z;  As[0][col4+3][r] = ra[p].w;
        Ws[0][col4+0][r] = sgnS*rw[p].x;  Ws[0][col4+1][r] = sgnS*rw[p].y;
        Ws[0][col4+2][r] = sgnS*rw[p].z;  Ws[0][col4+3][r] = sgnS*rw[p].w;
    }
    __syncthreads();

    unsigned long long acc[8][4];
    #pragma unroll
    for (int i = 0; i < 8; i++)
        #pragma unroll
        for (int j = 0; j < 4; j++) acc[i][j] = 0ULL;

    const int ty = tid >> 4, tx = tid & 15;

    for (int t = 0; t < ntiles; t++) {
        float sgn = 1.f;
        if (t + 1 < ntiles) {
            int k0 = (t + 1) * BK;
            const float* wb; int keff;
            if (ksplit && k0 >= ksplit) { wb = W1 + (size_t)n0 * ldw; keff = k0 - ksplit; sgn = w1sign; }
            else if (ksplit)            { wb = W0 + (size_t)n0 * ldw; keff = k0; }
            else                        { wb = WbaseN;                keff = k0; }
            #pragma unroll
            for (int p = 0; p < 2; p++) {
                ra[p] = *(const float4*)(Aptr + (size_t)(rowL + 64*p) * lda + k0 + col4);
                rw[p] = *(const float4*)(wb   + (size_t)(rowL + 64*p) * ldw + keff + col4);
            }
        }
        #pragma unroll
        for (int kk = 0; kk < BK; kk++) {
            float4 a0 = *(const float4*)&As[buf][kk][ty*8];
            float4 a1 = *(const float4*)&As[buf][kk][ty*8 + 4];
            ulonglong2 w01 = *(const ulonglong2*)&Ws[buf][kk][tx*8];
            ulonglong2 w23 = *(const ulonglong2*)&Ws[buf][kk][tx*8 + 4];
            unsigned long long bb0 = w01.x, bb1 = w01.y, bb2 = w23.x, bb3 = w23.y;
            float av[8] = {a0.x, a0.y, a0.z, a0.w, a1.x, a1.y, a1.z, a1.w};
            #pragma unroll
            for (int i = 0; i < 8; i++) {
                unsigned long long ai = pk2(av[i], av[i]);
                acc[i][0] = fma2(ai, bb0, acc[i][0]);
                acc[i][1] = fma2(ai, bb1, acc[i][1]);
                acc[i][2] = fma2(ai, bb2, acc[i][2]);
                acc[i][3] = fma2(ai, bb3, acc[i][3]);
            }
        }
        if (t + 1 < ntiles) {
            int nb = buf ^ 1;
            #pragma unroll
            for (int p = 0; p < 2; p++) {
                int r = rowL + 64*p;
                As[nb][col4+0][r] = ra[p].x;  As[nb][col4+1][r] = ra[p].y;
                As[nb][col4+2][r] = ra[p].z;  As[nb][col4+3][r] = ra[p].w;
                Ws[nb][col4+0][r] = sgn*rw[p].x;  Ws[nb][col4+1][r] = sgn*rw[p].y;
                Ws[nb][col4+2][r] = sgn*rw[p].z;  Ws[nb][col4+3][r] = sgn*rw[p].w;
            }
            __syncthreads();
            buf = nb;
        }
    }

    // ---- epilogue ----
    const int mrow = m0 + ty * 8;
    const int ncol = n0 + tx * 8;
    #pragma unroll
    for (int i = 0; i < 8; i++) {
        float c[8];
        #pragma unroll
        for (int j = 0; j < 4; j++) {
            union { unsigned long long u; float2 f; } cv;
            cv.u = acc[i][j];
            c[2*j]   = cv.f.x;
            c[2*j+1] = cv.f.y;
        }
        int gm = mrow + i;
        if (epi == 0) {
            if (biasb) {
                #pragma unroll
                for (int j = 0; j < 8; j++) c[j] += biasb[tx*8 + j];
            }
        } else if (epi == 1) {
            #pragma unroll
            for (int j = 0; j < 8; j++) c[j] *= epi_n[(ncol + j) & (HH - 1)];
        } else {
            #pragma unroll
            for (int j = 0; j < 8; j++) {
                float v = c[j] + epi_m[(size_t)gm * DD + ncol + j] * epi_n[ncol + j];
                c[j] = gelu_exact(v);
            }
        }
        *(float4*)(C + (size_t)gm * ldc + ncol)     = make_float4(c[0], c[1], c[2], c[3]);
        *(float4*)(C + (size_t)gm * ldc + ncol + 4) = make_float4(c[4], c[5], c[6], c[7]);
    }
}

// ---------------- scan: pass 1 (chunk-local summaries) ----------------
__global__ void scan_sum_kernel(const float* __restrict__ bu, int loff) {
    int h = blockIdx.x * blockDim.x + threadIdx.x;
    int c = blockIdx.y, b = blockIdx.z;
    float lre = g_lam_re[loff + h], lim = g_lam_im[loff + h];
    size_t base = ((size_t)(b * TT + c * CL)) * (2 * HH) + h;
    float are = 0.f, aim = 0.f;
    #pragma unroll 8
    for (int j = 0; j < CL; j++) {
        float ure = bu[base], uim = bu[base + HH];
        float nr = fmaf(are, lre, fmaf(-aim, lim, ure));
        float ni = fmaf(are, lim, fmaf(aim, lre, uim));
        are = nr; aim = ni;
        base += 2 * HH;
    }
    int o = (b * NCHUNK + c) * HH + h;
    g_sum_re[o] = are; g_sum_im[o] = aim;
}

// ---------------- scan: pass 2 (carry scan over chunks) ----------------
__global__ void scan_carry_kernel(int loff) {
    int idx = blockIdx.x * blockDim.x + threadIdx.x;  // B*H
    int b = idx >> 10, h = idx & (HH - 1);
    float lre = g_lam_re[loff + h], lim = g_lam_im[loff + h];
    float pre = lre, pim = lim;
    #pragma unroll
    for (int i = 0; i < 7; i++) {   // lam^128
        float nr = pre*pre - pim*pim;
        float ni = 2.f*pre*pim;
        pre = nr; pim = ni;
    }
    float cre = 0.f, cim = 0.f;
    #pragma unroll
    for (int c = 0; c < NCHUNK; c++) {
        int o = (b * NCHUNK + c) * HH + h;
        g_car_re[o] = cre; g_car_im[o] = cim;
        float sre = g_sum_re[o], sim = g_sum_im[o];
        float nr = cre*pre - cim*pim + sre;
        float ni = cre*pim + cim*pre + sim;
        cre = nr; cim = ni;
    }
}

// ---------------- scan: pass 3 (apply with correct carry, write hs) ----------------
__global__ void scan_apply_kernel(const float* __restrict__ bu,
                                  float* __restrict__ hs, int loff) {
    int h = blockIdx.x * blockDim.x + threadIdx.x;
    int c = blockIdx.y, b = blockIdx.z;
    float lre = g_lam_re[loff + h], lim = g_lam_im[loff + h];
    int o = (b * NCHUNK + c) * HH + h;
    float are = g_car_re[o], aim = g_car_im[o];
    size_t base = ((size_t)(b * TT + c * CL)) * (2 * HH) + h;
    #pragma unroll 8
    for (int j = 0; j < CL; j++) {
        float ure = bu[base], uim = bu[base + HH];
        float nr = fmaf(are, lre, fmaf(-aim, lim, ure));
        float ni = fmaf(are, lim, fmaf(aim, lre, uim));
        are = nr; aim = ni;
        hs[base]      = are;
        hs[base + HH] = aim;
        base += 2 * HH;
    }
}

// ---------------- GLU combine + residual:  x += g1 * sigmoid(g2) ----------------
__global__ void glu_combine_kernel(const float* __restrict__ g, float* __restrict__ x) {
    int i = blockIdx.x * blockDim.x + threadIdx.x;   // over MTOT*DD/4
    int m  = i / (DD / 4);
    int c4 = (i % (DD / 4)) * 4;
    const float* gr = g + (size_t)m * (2 * DD);
    float4 a  = *(const float4*)(gr + c4);
    float4 bq = *(const float4*)(gr + DD + c4);
    float4 xo = *(float4*)(x + (size_t)m * DD + c4);
    xo.x = fmaf(a.x, 1.f / (1.f + expf(-bq.x)), xo.x);
    xo.y = fmaf(a.y, 1.f / (1.f + expf(-bq.y)), xo.y);
    xo.z = fmaf(a.z, 1.f / (1.f + expf(-bq.z)), xo.z);
    xo.w = fmaf(a.w, 1.f / (1.f + expf(-bq.w)), xo.w);
    *(float4*)(x + (size_t)m * DD + c4) = xo;
}

// ---------------- launch ----------------
extern "C" void kernel_launch(void* const* d_in, const int* in_sizes, int n_in,
                              void* d_out, int out_size) {
    const float* inputs    = (const float*)d_in[0];
    const float* W_in      = (const float*)d_in[1];
    const float* b_in      = (const float*)d_in[2];
    const float* nu_log    = (const float*)d_in[3];
    const float* theta_log = (const float*)d_in[4];
    const float* B_re      = (const float*)d_in[5];
    const float* B_im      = (const float*)d_in[6];
    const float* C_re      = (const float*)d_in[7];
    const float* C_im      = (const float*)d_in[8];
    const float* D_diag    = (const float*)d_in[9];
    const float* ln_scale  = (const float*)d_in[10];
    const float* ln_bias   = (const float*)d_in[11];
    const float* w1        = (const float*)d_in[12];
    const float* b1        = (const float*)d_in[13];
    const float* w2        = (const float*)d_in[14];
    const float* b2        = (const float*)d_in[15];
    float* x = (float*)d_out;

    float *p_xn, *p_bu, *p_hs, *p_y, *p_g, *p_gam;
    cudaGetSymbolAddress((void**)&p_xn,  g_xn);
    cudaGetSymbolAddress((void**)&p_bu,  g_bu);
    cudaGetSymbolAddress((void**)&p_hs,  g_hs);
    cudaGetSymbolAddress((void**)&p_y,   g_y);
    cudaGetSymbolAddress((void**)&p_g,   g_g);
    cudaGetSymbolAddress((void**)&p_gam, g_gam);

    // params
    prep_kernel<<<(LNUM * HH) / 256, 256>>>(nu_log, theta_log);

    // input projection: x = inputs @ W_in^T + b_in   (M=8192, N=1024, K=256)
    gemm_f32<<<dim3(DD / BN, MTOT / BM), 256>>>(
        inputs, FF, W_in, nullptr, FF, 0, 0, 1.f,
        b_in, nullptr, x, DD, FF, 0, nullptr, nullptr);

    for (int l = 0; l < LNUM; l++) {
        // layernorm
        ln_kernel<<<MTOT, 256>>>(x, ln_scale + l * DD, ln_bias + l * DD, p_xn);

        // Bu = gamma * (xn @ [B_re;B_im]^T)   (N=2048, K=1024, N-split at 1024, epi=gamma scale)
        gemm_f32<<<dim3(2 * HH / BN, MTOT / BM), 256>>>(
            p_xn, DD,
            B_re + (size_t)l * HH * DD, B_im + (size_t)l * HH * DD, DD,
            HH, 0, 1.f, nullptr, nullptr,
            p_bu, 2 * HH, DD, 1, nullptr, p_gam + l * HH);

        // scan
        scan_sum_kernel  <<<dim3(HH / 256, NCHUNK, BB), 256>>>(p_bu, l * HH);
        scan_carry_kernel<<<(BB * HH) / 256, 256>>>(l * HH);
        scan_apply_kernel<<<dim3(HH / 256, NCHUNK, BB), 256>>>(p_bu, p_hs, l * HH);

        // y = gelu( hs @ [C_re | -C_im]^T + xn * D_diag )   (N=1024, K=2048, K-split at 1024)
        gemm_f32<<<dim3(DD / BN, MTOT / BM), 256>>>(
            p_hs, 2 * HH,
            C_re + (size_t)l * DD * HH, C_im + (size_t)l * DD * HH, HH,
            0, HH, -1.f, nullptr, nullptr,
            p_y, DD, 2 * HH, 2, p_xn, D_diag + l * DD);

        // g = y @ [w1;w2]^T + [b1;b2]   (N=2048, K=1024, N-split at 1024)
        gemm_f32<<<dim3(2 * DD / BN, MTOT / BM), 256>>>(
            p_y, DD,
            w1 + (size_t)l * DD * DD, w2 + (size_t)l * DD * DD, DD,
            DD, 0, 1.f, b1 + l * DD, b2 + l * DD,
            p_g, 2 * DD, DD, 0, nullptr, nullptr);

        // x += g1 * sigmoid(g2)
        glu_combine_kernel<<<(MTOT * DD / 4) / 256, 256>>>(p_g, x);
    }
    (void)in_sizes; (void)n_in; (void)out_size;
}